// round 1
// baseline (speedup 1.0000x reference)
#include <cuda_runtime.h>
#include <math.h>

#define BATCH  16
#define CC     64
#define MM     4096
#define NSPLIT 16
#define CHUNK  256
#define LDP    68   // padded row stride (floats) -> conflict-free float4 smem reads

// Deterministic scratch (no atomics): per-split partial Gram matrices + row sums.
__device__ float g_part[BATCH * NSPLIT * CC * CC];   // 4 MB
__device__ float g_rspart[BATCH * NSPLIT * CC];
__device__ float g_scale[BATCH * CC];

// ---------------------------------------------------------------------------
// Kernel 1: partial X·X^T per (batch, M-split) + partial row sums.
// grid (NSPLIT, BATCH), 256 threads. smem tile stored transposed: buf[k][row].
// ---------------------------------------------------------------------------
__global__ __launch_bounds__(256) void cov_kernel(const float* __restrict__ x) {
    __shared__ float buf[64 * LDP];
    const int split = blockIdx.x, b = blockIdx.y;
    const int t = threadIdx.x;
    const int tx = t & 15, ty = t >> 4;
    const float* xb = x + ((size_t)b * CC) * MM + split * CHUNK;

    float acc[4][4];
#pragma unroll
    for (int r = 0; r < 4; r++)
#pragma unroll
        for (int c = 0; c < 4; c++) acc[r][c] = 0.f;
    float rs = 0.f;

    for (int kk = 0; kk < CHUNK / 64; kk++) {
        __syncthreads();
        // Load 64 rows x 64 cols, transposed into buf[k][row]; coalesced global reads.
#pragma unroll
        for (int j = 0; j < 16; j++) {
            int idx = j * 256 + t;
            int row = idx >> 6, k = idx & 63;
            buf[k * LDP + row] = xb[(size_t)row * MM + kk * 64 + k];
        }
        __syncthreads();
        // Partial row sums: thread t covers row (t&63), k-quarter (t>>6).
        {
            int row = t & 63, k0 = (t >> 6) * 16;
            float s = 0.f;
#pragma unroll
            for (int kc = 0; kc < 16; kc++) s += buf[(k0 + kc) * LDP + row];
            rs += s;
        }
        // Rank-64 update: each thread owns a 4x4 tile of the 64x64 Gram matrix.
#pragma unroll 16
        for (int k = 0; k < 64; k++) {
            float4 a4 = *(const float4*)&buf[k * LDP + 4 * ty];
            float4 b4 = *(const float4*)&buf[k * LDP + 4 * tx];
            acc[0][0] += a4.x * b4.x; acc[0][1] += a4.x * b4.y;
            acc[0][2] += a4.x * b4.z; acc[0][3] += a4.x * b4.w;
            acc[1][0] += a4.y * b4.x; acc[1][1] += a4.y * b4.y;
            acc[1][2] += a4.y * b4.z; acc[1][3] += a4.y * b4.w;
            acc[2][0] += a4.z * b4.x; acc[2][1] += a4.z * b4.y;
            acc[2][2] += a4.z * b4.z; acc[2][3] += a4.z * b4.w;
            acc[3][0] += a4.w * b4.x; acc[3][1] += a4.w * b4.y;
            acc[3][2] += a4.w * b4.z; acc[3][3] += a4.w * b4.w;
        }
    }

    float* P = g_part + (((size_t)b * NSPLIT + split) << 12);
#pragma unroll
    for (int r = 0; r < 4; r++)
#pragma unroll
        for (int c = 0; c < 4; c++)
            P[(4 * ty + r) * 64 + 4 * tx + c] = acc[r][c];

    __syncthreads();
    buf[t] = rs;
    __syncthreads();
    if (t < 64) {
        float s = buf[t] + buf[t + 64] + buf[t + 128] + buf[t + 192];
        g_rspart[(b * NSPLIT + split) * 64 + t] = s;
    }
}

// ---------------------------------------------------------------------------
// 64x64x64 smem matmul: C = A @ B.  256 threads, 4x4 tiles.
// A reads broadcast across tx; B reads are conflict-free float4 (LDP=68).
// ---------------------------------------------------------------------------
__device__ __noinline__ void mm64(float* __restrict__ Cm, const float* __restrict__ A,
                                  const float* __restrict__ Bm, int tx, int ty) {
    __syncthreads();   // operands ready
    float acc[4][4];
#pragma unroll
    for (int r = 0; r < 4; r++)
#pragma unroll
        for (int c = 0; c < 4; c++) acc[r][c] = 0.f;

    const float* A0 = A + (4 * ty + 0) * LDP;
    const float* A1 = A + (4 * ty + 1) * LDP;
    const float* A2 = A + (4 * ty + 2) * LDP;
    const float* A3 = A + (4 * ty + 3) * LDP;

#pragma unroll 8
    for (int k = 0; k < 64; k++) {
        float a0 = A0[k], a1 = A1[k], a2 = A2[k], a3 = A3[k];
        float4 b4 = *(const float4*)&Bm[k * LDP + 4 * tx];
        acc[0][0] += a0 * b4.x; acc[0][1] += a0 * b4.y; acc[0][2] += a0 * b4.z; acc[0][3] += a0 * b4.w;
        acc[1][0] += a1 * b4.x; acc[1][1] += a1 * b4.y; acc[1][2] += a1 * b4.z; acc[1][3] += a1 * b4.w;
        acc[2][0] += a2 * b4.x; acc[2][1] += a2 * b4.y; acc[2][2] += a2 * b4.z; acc[2][3] += a2 * b4.w;
        acc[3][0] += a3 * b4.x; acc[3][1] += a3 * b4.y; acc[3][2] += a3 * b4.z; acc[3][3] += a3 * b4.w;
    }
    __syncthreads();   // all reads done before C is published
#pragma unroll
    for (int r = 0; r < 4; r++)
#pragma unroll
        for (int c = 0; c < 4; c++)
            Cm[(4 * ty + r) * LDP + 4 * tx + c] = acc[r][c];
    __syncthreads();   // C visible to everyone
}

// ---------------------------------------------------------------------------
// Kernel 2: per-batch covariance assembly + Newton-Schulz + center-tap convs.
// 16 blocks x 256 threads. Dynamic smem: 4 matrices of [64][LDP].
// ---------------------------------------------------------------------------
__global__ __launch_bounds__(256) void ns_kernel(const float* __restrict__ w1, const float* __restrict__ b1,
                                                 const float* __restrict__ w2, const float* __restrict__ b2) {
    extern __shared__ float sm[];
    float* S0 = sm;
    float* S1 = sm + 64 * LDP;
    float* S2 = sm + 2 * 64 * LDP;
    float* S3 = sm + 3 * 64 * LDP;
    __shared__ float svec[64];
    __shared__ float yv[64];
    __shared__ float red[8];
    __shared__ float snorm;

    const int b = blockIdx.x, t = threadIdx.x;
    const int tx = t & 15, ty = t >> 4;
    const float invM = 1.0f / (float)MM;

    // s = row sums (assembled from split partials)
    if (t < 64) {
        float s = 0.f;
        for (int sp = 0; sp < NSPLIT; sp++) s += g_rspart[(b * NSPLIT + sp) * 64 + t];
        svec[t] = s;
    }
    __syncthreads();

    // cov = Sxx/M - s s^T / M^2 ; accumulate normA = sum(cov)
    float lsum = 0.f;
    for (int e = 0; e < 16; e++) {
        int idx = e * 256 + t;
        int i = idx >> 6, j = idx & 63;
        float s = 0.f;
        for (int sp = 0; sp < NSPLIT; sp++)
            s += g_part[(((size_t)b * NSPLIT + sp) << 12) + idx];
        float cv = invM * s - (invM * invM) * svec[i] * svec[j];
        S0[i * LDP + j] = cv;
        lsum += cv;
    }
#pragma unroll
    for (int o = 16; o; o >>= 1) lsum += __shfl_xor_sync(0xffffffffu, lsum, o);
    if ((t & 31) == 0) red[t >> 5] = lsum;
    __syncthreads();
    if (t == 0) { float s = 0.f; for (int w = 0; w < 8; w++) s += red[w]; snorm = s; }
    __syncthreads();

    const float invN = 1.f / snorm;
    for (int e = 0; e < 16; e++) {
        int idx = e * 256 + t;
        int i = idx >> 6, j = idx & 63;
        float a = S0[i * LDP + j] * invN;
        S0[i * LDP + j] = a;
        float zy = 0.5f * (((i == j) ? 3.f : 0.f) - a);
        S3[i * LDP + j] = zy;   // ZY
        S2[i * LDP + j] = zy;   // Z = ZY
    }

    mm64(S1, S0, S3, tx, ty);   // Y = A @ ZY ; A (S0) now dead -> temp

    float* Y = S1; float* Z = S2; float* ZY = S3; float* T = S0;
    for (int it = 0; it < 3; it++) {
        mm64(T, Z, Y, tx, ty);                       // T = Z@Y
        for (int e = 0; e < 16; e++) {               // T <- ZYnew = 0.5(3I - T)
            int idx = e * 256 + t;
            int i = idx >> 6, j = idx & 63;
            T[i * LDP + j] = 0.5f * (((i == j) ? 3.f : 0.f) - T[i * LDP + j]);
        }
        __syncthreads();
        mm64(ZY, Y, T, tx, ty);                      // Ynew (old ZY buf) = Y @ ZYnew
        mm64(Y, T, Z, tx, ty);                       // Znew (old Y buf)  = ZYnew @ Z
        float* oY = Y; float* oZ = Z; float* oZY = ZY;
        Y = oZY; Z = oY; ZY = T; T = oZ;
    }

    mm64(T, Z, Y, tx, ty);                           // T = Z@Y (final)

    // y_vec = (0.5/64)*sqrt(normA) * (3u - u @ T), u = colsum(Y)
    if (t < 64) {
        float u = 0.f;
        for (int i = 0; i < 64; i++) u += Y[i * LDP + t];
        svec[t] = u;
    }
    __syncthreads();
    if (t < 64) {
        float dot = 0.f;
        for (int k = 0; k < 64; k++) dot += svec[k] * T[k * LDP + t];
        float c = (0.5f / 64.f) * sqrtf(snorm);
        yv[t] = c * (3.f * svec[t] - dot);
    }
    __syncthreads();
    // conv1 center tap + bias + relu
    if (t < 64) {
        float a = b1[t];
        for (int i = 0; i < 64; i++) a += w1[(t * 64 + i) * 9 + 4] * yv[i];
        svec[t] = fmaxf(a, 0.f);
    }
    __syncthreads();
    // conv2 center tap + bias + sigmoid
    if (t < 64) {
        float a = b2[t];
        for (int i = 0; i < 64; i++) a += w2[(t * 64 + i) * 9 + 4] * svec[i];
        g_scale[b * 64 + t] = 1.f / (1.f + expf(-a));
    }
}

// ---------------------------------------------------------------------------
// Kernel 3: out = scale[b,c] * x   (float4, HBM-bound)
// ---------------------------------------------------------------------------
__global__ __launch_bounds__(256) void scale_kernel(const float4* __restrict__ x4,
                                                    float4* __restrict__ out4) {
    int i = blockIdx.x * 256 + threadIdx.x;
    float s = g_scale[i >> 10];   // 4096 floats = 1024 float4 per (b,c)
    float4 v = x4[i];
    v.x *= s; v.y *= s; v.z *= s; v.w *= s;
    out4[i] = v;
}

extern "C" void kernel_launch(void* const* d_in, const int* in_sizes, int n_in,
                              void* d_out, int out_size) {
    const float* x  = (const float*)d_in[0];
    const float* w1 = (const float*)d_in[1];
    const float* b1 = (const float*)d_in[2];
    const float* w2 = (const float*)d_in[3];
    const float* b2 = (const float*)d_in[4];
    float* out = (float*)d_out;

    (void)in_sizes; (void)n_in; (void)out_size;

    cudaFuncSetAttribute(ns_kernel, cudaFuncAttributeMaxDynamicSharedMemorySize,
                         4 * 64 * LDP * (int)sizeof(float));

    dim3 gcov(NSPLIT, BATCH);
    cov_kernel<<<gcov, 256>>>(x);
    ns_kernel<<<BATCH, 256, 4 * 64 * LDP * (int)sizeof(float)>>>(w1, b1, w2, b2);
    scale_kernel<<<(BATCH * CC * MM / 4) / 256, 256>>>((const float4*)x, (float4*)out);
}